// round 8
// baseline (speedup 1.0000x reference)
#include <cuda_runtime.h>

// FlowComposite: flows [B,T,2,H,W] fp32 -> out [B,2,H,W] fp32.
// R8: in-thread vertical pair. Each thread advances pixels (x,y) and (x,y+1).
// Pixel B's TOP-row corners coincide with pixel A's BOTTOM-row corners when
// (ycB0, xcB0, xcB1) == (ycA1, xcA0, xcA1): reuse the already-loaded registers
// (bit-identical words), else fall back to the same loads. At t=0 the reuse is
// exact/unconditional (u=v=0). No shuffles (R7's overhead), lanes stay
// x-contiguous (keeps line spread minimal). 8x LDG.32 scalar gathers remain
// the addressing mode (R4/R5 showed wider loads lose on return-bw floors).

static constexpr int Bc = 8;
static constexpr int Tc = 12;
static constexpr int Hc = 544;
static constexpr int Wc = 960;
static constexpr int HW = Hc * Wc;

__global__ __launch_bounds__(256)
void flow_composite_kernel(const float* __restrict__ flows, float* __restrict__ out) {
    // Block tile: 64 x 8 pixels. Warp = 32 contiguous x, covering 2 pixel rows
    // per thread. warp&1 -> x half; warp>>1 -> row-pair within tile.
    const int lane = threadIdx.x & 31;
    const int warp = threadIdx.x >> 5;
    const int x  = (blockIdx.x << 6) + ((warp & 1) << 5) + lane;
    const int ya = (blockIdx.y << 3) + ((warp >> 1) << 1);   // pixel A row; B = ya+1
    const int b  = blockIdx.z;

    const float xf  = (float)x;
    const float yfA = (float)ya;
    const float yfB = (float)(ya + 1);

    const float* fb = flows + (unsigned)b * (Tc * 2 * HW);

    float uA, vA, uB, vB;

    // ---- t = 0: u=v=0 -> px = x-0.5, py = y-0.5; weights exactly 0.25*valid.
    // A corners: rows (ya-1, ya), cols (x-1, x). B corners: rows (ya, ya+1).
    // B's top row == A's bottom row, always.
    {
        const float* f0 = fb;            // u plane, t=0
        const float* f1 = fb + HW;       // v plane, t=0

        const int xm = max(x - 1, 0);
        const int rm = max(ya - 1, 0) * Wc;
        const int r0 = ya * Wc;
        const int r1 = (ya + 1) * Wc;    // ya+1 <= Hc-1 always (real pixel row)

        const float vx  = (x  >= 1) ? 1.0f : 0.0f;   // col x-1 validity
        const float vyA = (ya >= 1) ? 1.0f : 0.0f;   // row ya-1 validity

        // A: 8 loads
        const float a00 = __ldg(f0 + rm + xm);
        const float a10 = __ldg(f0 + rm + x);
        const float a01 = __ldg(f0 + r0 + xm);
        const float a11 = __ldg(f0 + r0 + x);
        const float c00 = __ldg(f1 + rm + xm);
        const float c10 = __ldg(f1 + rm + x);
        const float c01 = __ldg(f1 + r0 + xm);
        const float c11 = __ldg(f1 + r0 + x);
        // B bottom row: 4 loads (top row reuses a01,a11,c01,c11)
        const float aB01 = __ldg(f0 + r1 + xm);
        const float aB11 = __ldg(f0 + r1 + x);
        const float cB01 = __ldg(f1 + r1 + xm);
        const float cB11 = __ldg(f1 + r1 + x);

        const float wA00 = 0.25f * (vx * vyA);
        const float wA10 = 0.25f * vyA;
        const float wA01 = 0.25f * vx;
        const float wA11 = 0.25f;
        uA = ((wA00 * a00 + wA10 * a10) + wA01 * a01) + wA11 * a11;
        vA = ((wA00 * c00 + wA10 * c10) + wA01 * c01) + wA11 * c11;

        const float wB00 = 0.25f * vx;   // rows ya, ya+1 always valid
        const float wB10 = 0.25f;
        const float wB01 = 0.25f * vx;
        const float wB11 = 0.25f;
        uB = ((wB00 * a01 + wB10 * a11) + wB01 * aB01) + wB11 * aB11;
        vB = ((wB00 * c01 + wB10 * c11) + wB01 * cB01) + wB11 * cB11;
    }

    // ---- t = 1..11
    #pragma unroll
    for (int t = 1; t < Tc; ++t) {
        const float* f0 = fb + (unsigned)t * (2 * HW);   // u plane
        const float* f1 = f0 + HW;                       // v plane

        // ===== Pixel A =====
        const float pxA = xf + uA - 0.5f;
        const float pyA = yfA + vA - 0.5f;
        const int xA0 = __float2int_rd(pxA);
        const int yA0 = __float2int_rd(pyA);
        const float wxA1 = pxA - (float)xA0;
        const float wyA1 = pyA - (float)yA0;
        const float wxA0 = 1.0f - wxA1;
        const float wyA0 = 1.0f - wyA1;

        const bool vxA0 = (xA0 >= 0) && (xA0 <= Wc - 1);
        const bool vxA1 = (xA0 >= -1) && (xA0 <= Wc - 2);
        const bool vyA0 = (yA0 >= 0) && (yA0 <= Hc - 1);
        const bool vyA1 = (yA0 >= -1) && (yA0 <= Hc - 2);

        const int xcA0 = min(max(xA0, 0), Wc - 1);
        const int xcA1 = min(max(xA0 + 1, 0), Wc - 1);
        const int ycA0 = min(max(yA0, 0), Hc - 1);
        const int ycA1 = min(max(yA0 + 1, 0), Hc - 1);

        const float wA00 = wxA0 * wyA0 * ((vxA0 && vyA0) ? 1.0f : 0.0f);
        const float wA10 = wxA1 * wyA0 * ((vxA1 && vyA0) ? 1.0f : 0.0f);
        const float wA01 = wxA0 * wyA1 * ((vxA0 && vyA1) ? 1.0f : 0.0f);
        const float wA11 = wxA1 * wyA1 * ((vxA1 && vyA1) ? 1.0f : 0.0f);

        const int rA0 = ycA0 * Wc;
        const int rA1 = ycA1 * Wc;

        const float a00 = __ldg(f0 + rA0 + xcA0);
        const float a10 = __ldg(f0 + rA0 + xcA1);
        const float a01 = __ldg(f0 + rA1 + xcA0);
        const float a11 = __ldg(f0 + rA1 + xcA1);
        const float c00 = __ldg(f1 + rA0 + xcA0);
        const float c10 = __ldg(f1 + rA0 + xcA1);
        const float c01 = __ldg(f1 + rA1 + xcA0);
        const float c11 = __ldg(f1 + rA1 + xcA1);

        uA += ((wA00 * a00 + wA10 * a10) + wA01 * a01) + wA11 * a11;
        vA += ((wA00 * c00 + wA10 * c10) + wA01 * c01) + wA11 * c11;

        // ===== Pixel B =====
        const float pxB = xf + uB - 0.5f;
        const float pyB = yfB + vB - 0.5f;
        const int xB0 = __float2int_rd(pxB);
        const int yB0 = __float2int_rd(pyB);
        const float wxB1 = pxB - (float)xB0;
        const float wyB1 = pyB - (float)yB0;
        const float wxB0 = 1.0f - wxB1;
        const float wyB0 = 1.0f - wyB1;

        const bool vxB0 = (xB0 >= 0) && (xB0 <= Wc - 1);
        const bool vxB1 = (xB0 >= -1) && (xB0 <= Wc - 2);
        const bool vyB0 = (yB0 >= 0) && (yB0 <= Hc - 1);
        const bool vyB1 = (yB0 >= -1) && (yB0 <= Hc - 2);

        const int xcB0 = min(max(xB0, 0), Wc - 1);
        const int xcB1 = min(max(xB0 + 1, 0), Wc - 1);
        const int ycB0 = min(max(yB0, 0), Hc - 1);
        const int ycB1 = min(max(yB0 + 1, 0), Hc - 1);

        const float wB00 = wxB0 * wyB0 * ((vxB0 && vyB0) ? 1.0f : 0.0f);
        const float wB10 = wxB1 * wyB0 * ((vxB1 && vyB0) ? 1.0f : 0.0f);
        const float wB01 = wxB0 * wyB1 * ((vxB0 && vyB1) ? 1.0f : 0.0f);
        const float wB11 = wxB1 * wyB1 * ((vxB1 && vyB1) ? 1.0f : 0.0f);

        const int rB0 = ycB0 * Wc;
        const int rB1 = ycB1 * Wc;

        // Top row: reuse A's bottom-row registers when the addresses coincide.
        const bool share = (ycB0 == ycA1) && (xcB0 == xcA0) && (xcB1 == xcA1);
        float aB00, aB10, cB00, cB10;
        if (share) {
            aB00 = a01; aB10 = a11; cB00 = c01; cB10 = c11;
        } else {
            aB00 = __ldg(f0 + rB0 + xcB0);
            aB10 = __ldg(f0 + rB0 + xcB1);
            cB00 = __ldg(f1 + rB0 + xcB0);
            cB10 = __ldg(f1 + rB0 + xcB1);
        }

        // Bottom row: always load.
        const float aB01 = __ldg(f0 + rB1 + xcB0);
        const float aB11 = __ldg(f0 + rB1 + xcB1);
        const float cB01 = __ldg(f1 + rB1 + xcB0);
        const float cB11 = __ldg(f1 + rB1 + xcB1);

        uB += ((wB00 * aB00 + wB10 * aB10) + wB01 * aB01) + wB11 * aB11;
        vB += ((wB00 * cB00 + wB10 * cB10) + wB01 * cB01) + wB11 * cB11;
    }

    const int p = ya * Wc + x;
    float* ob = out + (unsigned)b * (2 * HW);
    ob[p]           = uA;
    ob[p + Wc]      = uB;
    ob[HW + p]      = vA;
    ob[HW + p + Wc] = vB;
}

extern "C" void kernel_launch(void* const* d_in, const int* in_sizes, int n_in,
                              void* d_out, int out_size) {
    const float* flows = (const float*)d_in[0];
    float* out = (float*)d_out;

    dim3 grid(Wc / 64, Hc / 8, Bc);   // 15 x 68 x 8, exact cover
    dim3 block(256);
    flow_composite_kernel<<<grid, block>>>(flows, out);
}

// round 9
// speedup vs baseline: 1.4026x; 1.4026x over previous
#include <cuda_runtime.h>

// FlowComposite: flows [B,T,2,H,W] fp32 -> out [B,2,H,W] fp32.
// R9: R6 core (scalar LDG.32 gathers -- measured cheapest divergent mode;
// 64x4 tile; exact coherent t=0 case) + ALU trim: validity folded into the
// per-axis weights (wx' = vx ? wx : 0; w = wx'*wy' -- bit-exact, same single
// rounding of wx*wy), and x-0.5 hoisted. Sharing/wide-load/interleave
// variants all measured slower (R3-R8); fp16 staging excluded by the chain's
// ~1e3 error amplification (R5 evidence).

static constexpr int Bc = 8;
static constexpr int Tc = 12;
static constexpr int Hc = 544;
static constexpr int Wc = 960;
static constexpr int HW = Hc * Wc;

__global__ __launch_bounds__(256)
void flow_composite_kernel(const float* __restrict__ flows, float* __restrict__ out) {
    // 64x4 pixel tile per block (keeps vertical gather reuse in one L1)
    const int x = (blockIdx.x << 6) + (threadIdx.x & 63);
    const int y = (blockIdx.y << 2) + (threadIdx.x >> 6);
    const int b = blockIdx.z;

    const float xh = (float)x - 0.5f;   // hoisted: px = xh + u
    const float yh = (float)y - 0.5f;

    const float* fb = flows + (unsigned)b * (Tc * 2 * HW);

    // ---- t = 0: u=v=0 exactly -> px = x-0.5 -> weights exactly 0.25*valid,
    // corners (x-1,x)x(y-1,y): fully coherent loads.
    float u, v;
    {
        const float* f0 = fb;
        const float* f1 = fb + HW;

        const int xm = max(x - 1, 0);
        const int ym = max(y - 1, 0);
        const int r0 = ym * Wc;
        const int r1 = y * Wc;

        const float vx = (x >= 1) ? 1.0f : 0.0f;
        const float vy = (y >= 1) ? 1.0f : 0.0f;
        const float w00 = 0.25f * (vx * vy);
        const float w10 = 0.25f * vy;
        const float w01 = 0.25f * vx;
        const float w11 = 0.25f;

        const float a00 = __ldg(f0 + r0 + xm);
        const float a10 = __ldg(f0 + r0 + x);
        const float a01 = __ldg(f0 + r1 + xm);
        const float a11 = __ldg(f0 + r1 + x);
        const float b00 = __ldg(f1 + r0 + xm);
        const float b10 = __ldg(f1 + r0 + x);
        const float b01 = __ldg(f1 + r1 + xm);
        const float b11 = __ldg(f1 + r1 + x);

        u = ((w00 * a00 + w10 * a10) + w01 * a01) + w11 * a11;
        v = ((w00 * b00 + w10 * b10) + w01 * b01) + w11 * b11;
    }

    // ---- t = 1..11: divergent scalar gathers, folded-validity weights.
    #pragma unroll
    for (int t = 1; t < Tc; ++t) {
        const float* f0 = fb + (unsigned)t * (2 * HW);   // u plane
        const float* f1 = f0 + HW;                       // v plane

        const float px = xh + u;
        const float py = yh + v;

        const int x0 = __float2int_rd(px);
        const int y0 = __float2int_rd(py);

        const float wx1 = px - (float)x0;
        const float wy1 = py - (float)y0;
        const float wx0 = 1.0f - wx1;
        const float wy0 = 1.0f - wy1;

        // Fold validity into axis weights (exact: x1.0 / x0.0).
        const float gx0 = ((x0 >= 0)  && (x0 <= Wc - 1)) ? wx0 : 0.0f;
        const float gx1 = ((x0 >= -1) && (x0 <= Wc - 2)) ? wx1 : 0.0f;
        const float gy0 = ((y0 >= 0)  && (y0 <= Hc - 1)) ? wy0 : 0.0f;
        const float gy1 = ((y0 >= -1) && (y0 <= Hc - 2)) ? wy1 : 0.0f;

        const float w00 = gx0 * gy0;
        const float w10 = gx1 * gy0;
        const float w01 = gx0 * gy1;
        const float w11 = gx1 * gy1;

        const int xc0 = min(max(x0, 0), Wc - 1);
        const int xc1 = min(max(x0 + 1, 0), Wc - 1);
        const int yc0 = min(max(y0, 0), Hc - 1);
        const int yc1 = min(max(y0 + 1, 0), Hc - 1);

        const int r0 = yc0 * Wc;
        const int r1 = yc1 * Wc;
        const int i00 = r0 + xc0;
        const int i10 = r0 + xc1;
        const int i01 = r1 + xc0;
        const int i11 = r1 + xc1;

        // 8 independent scalar gathers -> MLP 8.
        const float a00 = __ldg(f0 + i00);
        const float a10 = __ldg(f0 + i10);
        const float a01 = __ldg(f0 + i01);
        const float a11 = __ldg(f0 + i11);
        const float b00 = __ldg(f1 + i00);
        const float b10 = __ldg(f1 + i10);
        const float b01 = __ldg(f1 + i01);
        const float b11 = __ldg(f1 + i11);

        // Same summation order as reference: ((c00 + c10) + c01) + c11
        const float s0 = ((w00 * a00 + w10 * a10) + w01 * a01) + w11 * a11;
        const float s1 = ((w00 * b00 + w10 * b10) + w01 * b01) + w11 * b11;

        u += s0;
        v += s1;
    }

    const int p = y * Wc + x;
    float* ob = out + (unsigned)b * (2 * HW);
    ob[p]      = u;
    ob[HW + p] = v;
}

extern "C" void kernel_launch(void* const* d_in, const int* in_sizes, int n_in,
                              void* d_out, int out_size) {
    const float* flows = (const float*)d_in[0];
    float* out = (float*)d_out;

    dim3 grid(Wc / 64, Hc / 4, Bc);   // exact cover, no tails
    dim3 block(256);
    flow_composite_kernel<<<grid, block>>>(flows, out);
}

// round 10
// speedup vs baseline: 1.4095x; 1.0049x over previous
#include <cuda_runtime.h>

// FlowComposite: flows [B,T,2,H,W] fp32 -> out [B,2,H,W] fp32.
// R10 (final form): R6's bit-exact core -- scalar LDG.32 gathers (measured
// cheapest divergent addressing mode on sm_103a; .64/.128 merges lose to
// per-request return-bandwidth floors), exact coherent t=0 case, reference
// rounding order px=(x+u)-0.5 (the R9 hoist perturbed rounding and cost
// rel_err 4.3e-4 via the chain's ~1e3 amplification -- reverted).
// Exact validity-fold kept (x1.0/x0.0 weights, no rounding change).
// Tile 32x8 (warps stay 32 contiguous line-aligned x; taller tile gives one
// more round of in-L1 vertical reuse; L2 was 36% from cross-SM refetch).
// Kernel is at the data-dependent L1tex gather-wavefront roofline (~95%).

static constexpr int Bc = 8;
static constexpr int Tc = 12;
static constexpr int Hc = 544;
static constexpr int Wc = 960;
static constexpr int HW = Hc * Wc;

__global__ __launch_bounds__(256)
void flow_composite_kernel(const float* __restrict__ flows, float* __restrict__ out) {
    // 32x8 pixel tile per block; warp = 32 contiguous x (128B-aligned base).
    const int x = (blockIdx.x << 5) + (threadIdx.x & 31);
    const int y = (blockIdx.y << 3) + (threadIdx.x >> 5);
    const int b = blockIdx.z;

    const float xf = (float)x;
    const float yf = (float)y;

    const float* fb = flows + (unsigned)b * (Tc * 2 * HW);

    // ---- t = 0: u=v=0 exactly -> px = x-0.5 -> weights exactly 0.25*valid,
    // corners (x-1,x)x(y-1,y): fully coherent loads.
    float u, v;
    {
        const float* f0 = fb;
        const float* f1 = fb + HW;

        const int xm = max(x - 1, 0);
        const int ym = max(y - 1, 0);
        const int r0 = ym * Wc;
        const int r1 = y * Wc;

        const float vx = (x >= 1) ? 1.0f : 0.0f;
        const float vy = (y >= 1) ? 1.0f : 0.0f;
        const float w00 = 0.25f * (vx * vy);
        const float w10 = 0.25f * vy;
        const float w01 = 0.25f * vx;
        const float w11 = 0.25f;

        const float a00 = __ldg(f0 + r0 + xm);
        const float a10 = __ldg(f0 + r0 + x);
        const float a01 = __ldg(f0 + r1 + xm);
        const float a11 = __ldg(f0 + r1 + x);
        const float b00 = __ldg(f1 + r0 + xm);
        const float b10 = __ldg(f1 + r0 + x);
        const float b01 = __ldg(f1 + r1 + xm);
        const float b11 = __ldg(f1 + r1 + x);

        u = ((w00 * a00 + w10 * a10) + w01 * a01) + w11 * a11;
        v = ((w00 * b00 + w10 * b10) + w01 * b01) + w11 * b11;
    }

    // ---- t = 1..11: divergent scalar gathers, reference rounding order.
    #pragma unroll
    for (int t = 1; t < Tc; ++t) {
        const float* f0 = fb + (unsigned)t * (2 * HW);   // u plane
        const float* f1 = f0 + HW;                       // v plane

        // Reference order: (x + u) - 0.5 (do NOT hoist the -0.5).
        const float px = (xf + u) - 0.5f;
        const float py = (yf + v) - 0.5f;

        const int x0 = __float2int_rd(px);
        const int y0 = __float2int_rd(py);

        const float wx1 = px - (float)x0;
        const float wy1 = py - (float)y0;
        const float wx0 = 1.0f - wx1;
        const float wy0 = 1.0f - wy1;

        // Fold validity into axis weights (exact: x1.0 / x0.0).
        const float gx0 = ((x0 >= 0)  && (x0 <= Wc - 1)) ? wx0 : 0.0f;
        const float gx1 = ((x0 >= -1) && (x0 <= Wc - 2)) ? wx1 : 0.0f;
        const float gy0 = ((y0 >= 0)  && (y0 <= Hc - 1)) ? wy0 : 0.0f;
        const float gy1 = ((y0 >= -1) && (y0 <= Hc - 2)) ? wy1 : 0.0f;

        const float w00 = gx0 * gy0;
        const float w10 = gx1 * gy0;
        const float w01 = gx0 * gy1;
        const float w11 = gx1 * gy1;

        const int xc0 = min(max(x0, 0), Wc - 1);
        const int xc1 = min(max(x0 + 1, 0), Wc - 1);
        const int yc0 = min(max(y0, 0), Hc - 1);
        const int yc1 = min(max(y0 + 1, 0), Hc - 1);

        const int r0 = yc0 * Wc;
        const int r1 = yc1 * Wc;
        const int i00 = r0 + xc0;
        const int i10 = r0 + xc1;
        const int i01 = r1 + xc0;
        const int i11 = r1 + xc1;

        // 8 independent scalar gathers -> MLP 8.
        const float a00 = __ldg(f0 + i00);
        const float a10 = __ldg(f0 + i10);
        const float a01 = __ldg(f0 + i01);
        const float a11 = __ldg(f0 + i11);
        const float b00 = __ldg(f1 + i00);
        const float b10 = __ldg(f1 + i10);
        const float b01 = __ldg(f1 + i01);
        const float b11 = __ldg(f1 + i11);

        // Same summation order as reference: ((c00 + c10) + c01) + c11
        const float s0 = ((w00 * a00 + w10 * a10) + w01 * a01) + w11 * a11;
        const float s1 = ((w00 * b00 + w10 * b10) + w01 * b01) + w11 * b11;

        u += s0;
        v += s1;
    }

    const int p = y * Wc + x;
    float* ob = out + (unsigned)b * (2 * HW);
    ob[p]      = u;
    ob[HW + p] = v;
}

extern "C" void kernel_launch(void* const* d_in, const int* in_sizes, int n_in,
                              void* d_out, int out_size) {
    const float* flows = (const float*)d_in[0];
    float* out = (float*)d_out;

    dim3 grid(Wc / 32, Hc / 8, Bc);   // 30 x 68 x 8, exact cover
    dim3 block(256);
    flow_composite_kernel<<<grid, block>>>(flows, out);
}